// round 7
// baseline (speedup 1.0000x reference)
#include <cuda_runtime.h>

// Problem constants
#define BB 16
#define DD 16
#define HH 128
#define WW 160
#define ROW4   (WW*4)        // 640 float4 per (b,h) row in (B,H,W,D) layout
#define TH     8             // output rows per block
#define NCHUNK (HH/TH)       // 16
#define PLANE4 (HH*WW*4)
#define NV4    (BB*HH*WW*4)
#define HW     (HH*WW)

// Chebyshev on spectrum [1, 9]
#define THETA 5.0
#define DELTA 4.0

#define MODE_INIT 0
#define MODE_MID  1
#define MODE_LAST 2

__device__ float4 g_bt[NV4];      // b in (B,H,W,D) layout
__device__ float4 g_x[2][NV4];    // x3/x9 and x6

extern __shared__ float4 s_mem[];   // xr[4][ROW4], rg[4][ROW4], u2[4][ROW4] = 120KB

// -------------------- fused triple Chebyshev step --------------------
// r = b - A x ;  x_next = G1*x + G2*x_km3 + [k0*r + A(k1*r + k2*(A r))]
// (k_i = Gc * q3 coefficients, folded on host).
// One barrier per row-epoch; ring slots indexed by row & 3 (R5 scheme).
// Collision audit (mod 4, within one barrier interval = S1..S3(hh) + S0(hh+1)):
//   xr: S0(hh+1) writes (hh+1)=(hh-3); S1(hh) reads (hh-2..hh)  -> disjoint
//   rg: S1(hh) writes (hh-1); S2(hh) reads (hh-4..hh-2)         -> disjoint
//   u2: S2(hh) writes (hh-3); S3(hh) reads (hh-6..hh-4)         -> disjoint
template<int MODE>
__global__ void __launch_bounds__(ROW4, 1)
cheb_tri(const float4* __restrict__ x_in,
         const float4* x_km3,               // may alias x_out (read@output elem only)
         const float4* __restrict__ b_in,
         const float*  __restrict__ ae,
         const float*  __restrict__ wxy,
         float4* x_out,
         float4* __restrict__ bt_w,
         float*  __restrict__ out_t,
         float G1, float G2, float k0, float k1, float k2)
{
    float4 (*xr)[ROW4] = (float4 (*)[ROW4])(s_mem);
    float4 (*rg)[ROW4] = (float4 (*)[ROW4])(s_mem + 4*ROW4);
    float4 (*u2)[ROW4] = (float4 (*)[ROW4])(s_mem + 8*ROW4);

    const int t  = threadIdx.x;         // 640
    const int w  = t >> 2;
    const int q  = t & 3;               // float4 quarter -> channels q*4..q*4+3
    const int blk = blockIdx.x;
    const int bi  = blk / NCHUNK;
    const int h0  = (blk - bi*NCHUNK) * TH;
    const size_t base = (size_t)bi * PLANE4;
    const float* wx = wxy + ((size_t)bi*2    )*HW;
    const float* wy = wxy + ((size_t)bi*2 + 1)*HW;
    const float4 z = make_float4(0.f,0.f,0.f,0.f);

    // per-thread center FIFOs: at epoch hh, rf_k = r(hh-2-k), xf_k = x(hh-1-k)
    float4 rf0=z, rf1=z, rf2=z, rf3=z;
    float4 xf0=z, xf1=z, xf2=z, xf3=z, xf4=z;

    #pragma unroll 1
    for (int hh = h0-3; hh <= h0+TH+4; ++hh) {
        // ---- S0: publish x row hh (rows h0-3 .. h0+TH+2)
        float4 xv = z;
        if (hh <= h0+TH+2) {
            if (hh >= 0 && hh < HH) {
                if (MODE == MODE_INIT) {
                    const float* src = ae + ((size_t)(bi*DD + q*4)*HH + hh)*WW + w;
                    xv.x = src[0];
                    xv.y = src[HW];
                    xv.z = src[2*HW];
                    xv.w = src[3*(size_t)HW];
                    bt_w[base + (size_t)hh*ROW4 + t] = xv;   // transposed b side-product
                } else {
                    xv = x_in[base + (size_t)hh*ROW4 + t];
                }
            }
            xr[hh & 3][t] = xv;
        }
        __syncthreads();

        // ---- S1: r = b - A x at row j = hh-1 (rows h0-2 .. h0+TH+1)
        float4 rv = z;
        {
            const int j = hh - 1;
            if (j >= h0-2 && j <= h0+TH+1) {
                if (j >= 0 && j < HH) {
                    float4 sc = xr[j & 3][t];
                    float4 sl = (w > 0)     ? xr[j & 3][t-4] : z;
                    float4 sr = (w < WW-1)  ? xr[j & 3][t+4] : z;
                    float4 su = xr[(j-1) & 3][t];
                    float4 sd = xr[(j+1) & 3][t];

                    int woff  = j*WW + w;
                    float wxm = (w > 0)     ? wx[woff-1]  : 0.f;
                    float wxp = (w < WW-1)  ? wx[woff]    : 0.f;
                    float wym = (j > 0)     ? wy[woff-WW] : 0.f;
                    float wyp = (j < HH-1)  ? wy[woff]    : 0.f;

                    float4 bv;
                    if (MODE == MODE_INIT) bv = sc;   // b == x0
                    else bv = b_in[base + (size_t)j*ROW4 + t];

                    rv.x = bv.x - (sc.x + wxm*(sc.x-sl.x) - wxp*(sr.x-sc.x) + wym*(sc.x-su.x) - wyp*(sd.x-sc.x));
                    rv.y = bv.y - (sc.y + wxm*(sc.y-sl.y) - wxp*(sr.y-sc.y) + wym*(sc.y-su.y) - wyp*(sd.y-sc.y));
                    rv.z = bv.z - (sc.z + wxm*(sc.z-sl.z) - wxp*(sr.z-sc.z) + wym*(sc.z-su.z) - wyp*(sd.z-sc.z));
                    rv.w = bv.w - (sc.w + wxm*(sc.w-sl.w) - wxp*(sr.w-sc.w) + wym*(sc.w-su.w) - wyp*(sd.w-sc.w));
                }
                rg[j & 3][t] = rv;
            }
        }

        // ---- S2: u2 = k1*r + k2*(A r) at row j = hh-3 (rows h0-1 .. h0+TH)
        {
            const int j = hh - 3;
            if (j >= h0-1 && j <= h0+TH) {
                float4 uv = z;
                if (j >= 0 && j < HH) {
                    float4 rc = rg[j & 3][t];
                    float4 rl = (w > 0)     ? rg[j & 3][t-4] : z;
                    float4 rr = (w < WW-1)  ? rg[j & 3][t+4] : z;
                    float4 ru = rg[(j-1) & 3][t];
                    float4 rd = rg[(j+1) & 3][t];

                    int woff  = j*WW + w;
                    float wxm = (w > 0)     ? wx[woff-1]  : 0.f;
                    float wxp = (w < WW-1)  ? wx[woff]    : 0.f;
                    float wym = (j > 0)     ? wy[woff-WW] : 0.f;
                    float wyp = (j < HH-1)  ? wy[woff]    : 0.f;

                    float4 ar;
                    ar.x = rc.x + wxm*(rc.x-rl.x) - wxp*(rr.x-rc.x) + wym*(rc.x-ru.x) - wyp*(rd.x-rc.x);
                    ar.y = rc.y + wxm*(rc.y-rl.y) - wxp*(rr.y-rc.y) + wym*(rc.y-ru.y) - wyp*(rd.y-rc.y);
                    ar.z = rc.z + wxm*(rc.z-rl.z) - wxp*(rr.z-rc.z) + wym*(rc.z-ru.z) - wyp*(rd.z-rc.z);
                    ar.w = rc.w + wxm*(rc.w-rl.w) - wxp*(rr.w-rc.w) + wym*(rc.w-ru.w) - wyp*(rd.w-rc.w);

                    // rf1 == r(hh-3) == this row's center r
                    uv.x = k1*rf1.x + k2*ar.x;
                    uv.y = k1*rf1.y + k2*ar.y;
                    uv.z = k1*rf1.z + k2*ar.z;
                    uv.w = k1*rf1.w + k2*ar.w;
                }
                u2[j & 3][t] = uv;
            }
        }

        // ---- S3: output at row j = hh-5 (rows h0 .. h0+TH-1)
        {
            const int j = hh - 5;
            if (j >= h0 && j < h0+TH) {
                float4 uc = u2[j & 3][t];
                float4 ul = (w > 0)     ? u2[j & 3][t-4] : z;
                float4 ur = (w < WW-1)  ? u2[j & 3][t+4] : z;
                float4 uu = u2[(j-1) & 3][t];
                float4 ud = u2[(j+1) & 3][t];

                int woff  = j*WW + w;
                float wxm = (w > 0)     ? wx[woff-1]  : 0.f;
                float wxp = (w < WW-1)  ? wx[woff]    : 0.f;
                float wym = (j > 0)     ? wy[woff-WW] : 0.f;
                float wyp = (j < HH-1)  ? wy[woff]    : 0.f;

                float4 au;
                au.x = uc.x + wxm*(uc.x-ul.x) - wxp*(ur.x-uc.x) + wym*(uc.x-uu.x) - wyp*(ud.x-uc.x);
                au.y = uc.y + wxm*(uc.y-ul.y) - wxp*(ur.y-uc.y) + wym*(uc.y-uu.y) - wyp*(ud.y-uc.y);
                au.z = uc.z + wxm*(uc.z-ul.z) - wxp*(ur.z-uc.z) + wym*(uc.z-uu.z) - wyp*(ud.z-uc.z);
                au.w = uc.w + wxm*(uc.w-ul.w) - wxp*(ur.w-uc.w) + wym*(uc.w-uu.w) - wyp*(ud.w-uc.w);

                size_t idx = base + (size_t)j*ROW4 + t;
                float4 xc = xf4;          // x(hh-5) from register FIFO
                float4 on;
                if (MODE == MODE_INIT) {
                    on.x = G1*xc.x + k0*rf3.x + au.x;
                    on.y = G1*xc.y + k0*rf3.y + au.y;
                    on.z = G1*xc.z + k0*rf3.z + au.z;
                    on.w = G1*xc.w + k0*rf3.w + au.w;
                } else {
                    float4 xm = x_km3[idx];      // load BEFORE aliased store
                    on.x = G1*xc.x + G2*xm.x + k0*rf3.x + au.x;
                    on.y = G1*xc.y + G2*xm.y + k0*rf3.y + au.y;
                    on.z = G1*xc.z + G2*xm.z + k0*rf3.z + au.z;
                    on.w = G1*xc.w + G2*xm.w + k0*rf3.w + au.w;
                }

                if (MODE == MODE_LAST) {
                    // direct (B,D,H,W) store: 8-lane runs of consecutive w per
                    // channel -> full 32B sectors.
                    float* o = out_t + ((size_t)(bi*DD + q*4)*HH + j)*WW + w;
                    o[0]              = on.x;
                    o[HW]             = on.y;
                    o[2*HW]           = on.z;
                    o[3*(size_t)HW]   = on.w;
                } else {
                    x_out[idx] = on;
                }
            }
        }

        // ---- FIFO shifts
        rf3 = rf2; rf2 = rf1; rf1 = rf0; rf0 = rv;
        xf4 = xf3; xf3 = xf2; xf2 = xf1; xf1 = xf0; xf0 = xv;
    }
}

// -------------------- launch --------------------
extern "C" void kernel_launch(void* const* d_in, const int* in_sizes, int n_in,
                              void* d_out, int out_size)
{
    const float* ae  = (const float*)d_in[0];   // (B,D,H,W)
    const float* wxy = (const float*)d_in[1];   // (B,2,H,W)
    float* out = (float*)d_out;                 // (B,D,H,W)

    float4 *bt, *xb;
    cudaGetSymbolAddress((void**)&bt, g_bt);
    cudaGetSymbolAddress((void**)&xb, g_x);
    float4* xA = xb;          // x3, later x9 (in-place)
    float4* xB = xb + NV4;    // x6

    const int SMEM = 12 * ROW4 * (int)sizeof(float4);   // 122880
    cudaFuncSetAttribute(cheb_tri<MODE_INIT>, cudaFuncAttributeMaxDynamicSharedMemorySize, SMEM);
    cudaFuncSetAttribute(cheb_tri<MODE_MID>,  cudaFuncAttributeMaxDynamicSharedMemorySize, SMEM);
    cudaFuncSetAttribute(cheb_tri<MODE_LAST>, cudaFuncAttributeMaxDynamicSharedMemorySize, SMEM);

    // Chebyshev values at sigma = theta/delta = 1.25
    const double t3  = 4.0*1.25*1.25*1.25 - 3.0*1.25;     // 4.0625
    const double t6  = 2.0*t3*t3 - 1.0;
    const double t9  = 2.0*t3*t6 - t3;
    const double t12 = 2.0*t3*t9 - t6;
    // q3(a) = (T3((theta-a)/delta) - t3)/a = c0 + c1 a + c2 a^2
    const double c0 = -63.0/16.0, c1 = 15.0/16.0, c2 = -1.0/16.0;

    const int GRID = BB * NCHUNK;   // 256 blocks x 640 threads

    // L1: x3 = x0 - (1/t3) q3(A) r0,  x0 = b (reads ae, emits bt)
    {
        double Gc = -1.0 / t3;
        cheb_tri<MODE_INIT><<<GRID, ROW4, SMEM>>>(nullptr, nullptr, nullptr, ae, wxy,
            xA, bt, nullptr,
            1.f, 0.f, (float)(Gc*c0), (float)(Gc*c1), (float)(Gc*c2));
    }
    // L2: x6 = (2 t3^2/t6) x3 - (1/t6) x0 - (2 t3/t6) q3(A) r3
    {
        double Gc = -2.0*t3/t6;
        cheb_tri<MODE_MID><<<GRID, ROW4, SMEM>>>(xA, bt, bt, nullptr, wxy,
            xB, nullptr, nullptr,
            (float)(2.0*t3*t3/t6), (float)(-1.0/t6),
            (float)(Gc*c0), (float)(Gc*c1), (float)(Gc*c2));
    }
    // L3: x9 = (2 t3 t6/t9) x6 - (t3/t9) x3 - (2 t6/t9) q3(A) r6   (in-place over x3)
    {
        double Gc = -2.0*t6/t9;
        cheb_tri<MODE_MID><<<GRID, ROW4, SMEM>>>(xB, xA, bt, nullptr, wxy,
            xA, nullptr, nullptr,
            (float)(2.0*t3*t6/t9), (float)(-t3/t9),
            (float)(Gc*c0), (float)(Gc*c1), (float)(Gc*c2));
    }
    // L4: x12 = (2 t3 t9/t12) x9 - (t6/t12) x6 - (2 t9/t12) q3(A) r9 -> out (B,D,H,W)
    {
        double Gc = -2.0*t9/t12;
        cheb_tri<MODE_LAST><<<GRID, ROW4, SMEM>>>(xA, xB, bt, nullptr, wxy,
            nullptr, nullptr, out,
            (float)(2.0*t3*t9/t12), (float)(-t6/t12),
            (float)(Gc*c0), (float)(Gc*c1), (float)(Gc*c2));
    }
}

// round 8
// speedup vs baseline: 1.1640x; 1.1640x over previous
#include <cuda_runtime.h>
#include <math.h>

// Problem constants
#define BB 16
#define DD 16
#define HH 128
#define WW 160
#define ROW4   (WW*4)        // 640 float4 per (b,h) row in (B,H,W,D) layout
#define TH     8             // output rows per block
#define NCHUNK (HH/TH)       // 16
#define PLANE4 (HH*WW*4)
#define NV4    (BB*HH*WW*4)
#define HW     (HH*WW)

#define MODE_INIT 0
#define MODE_MID  1
#define MODE_LAST 2

__device__ float4 g_bt[NV4];      // b in (B,H,W,D) layout
__device__ float4 g_x[2][NV4];    // x ping-pong

extern __shared__ float4 s_mem[];   // xr[3][ROW4] + r1[4][ROW4] + r2[4][ROW4] = 110KB

// slot for depth-3 ring (row can be as low as -6)
#define S3SLOT(rr) (((rr) + 6) % 3)

// A z = z + weighted 5-pt Laplacian(z)
#define AX4(o, c, l, r, u, d) \
    o.x = c.x + wxm*(c.x-l.x) - wxp*(r.x-c.x) + wym*(c.x-u.x) - wyp*(d.x-c.x); \
    o.y = c.y + wxm*(c.y-l.y) - wxp*(r.y-c.y) + wym*(c.y-u.y) - wyp*(d.y-c.y); \
    o.z = c.z + wxm*(c.z-l.z) - wxp*(r.z-c.z) + wym*(c.z-u.z) - wyp*(d.z-c.z); \
    o.w = c.w + wxm*(c.w-l.w) - wxp*(r.w-c.w) + wym*(c.w-u.w) - wyp*(d.w-c.w);

#define LOADW(j) \
    { int woff = (j)*WW + w; \
      wxm = (w > 0)      ? wx[woff-1]  : 0.f; \
      wxp = (w < WW-1)   ? wx[woff]    : 0.f; \
      wym = ((j) > 0)    ? wy[woff-WW] : 0.f; \
      wyp = ((j) < HH-1) ? wy[woff]    : 0.f; }

// -------------------- fused triple Richardson step --------------------
// x1 = x  + ta*(b - A x)    (S1, row hh-1, ring r1)
// x2 = x1 + tb*(b - A x1)   (S2, row hh-3, ring r2)
// x3 = x2 + tc*(b - A x2)   (S3, row hh-5, output)
// Two __syncthreads per epoch: one after the x-row publish (lets the x ring be
// depth 3), one at end of epoch. Ring collision audit:
//  xr (mod 3): epoch-hh interval-B reads rows hh-2..hh (distinct mod 3); next
//    S0 write row hh+1 == hh-2 mod 3 is in interval-A, separated by end sync.
//  r1 (mod 4): S1 writes hh-1; S2 reads hh-4..hh-2 == {hh,hh-3,hh-2} distinct.
//  r2 (mod 4): S2 writes hh-3; S3 reads hh-6..hh-4 == {hh-2,hh-1,hh} distinct.
// b carried center-only in a register FIFO (bf0=b(hh-2) .. bf3=b(hh-5)).
template<int MODE>
__global__ void __launch_bounds__(ROW4, 2)
rich_tri(const float4* __restrict__ x_in,
         const float4* __restrict__ b_in,
         const float*  __restrict__ ae,
         const float*  __restrict__ wxy,
         float4* __restrict__ x_out,
         float4* __restrict__ bt_w,
         float*  __restrict__ out_t,
         float ta, float tb, float tc)
{
    float4 (*xr)[ROW4] = (float4 (*)[ROW4])(s_mem);            // depth 3
    float4 (*r1)[ROW4] = (float4 (*)[ROW4])(s_mem + 3*ROW4);   // depth 4
    float4 (*r2)[ROW4] = (float4 (*)[ROW4])(s_mem + 7*ROW4);   // depth 4

    const int t  = threadIdx.x;         // 640
    const int w  = t >> 2;
    const int q  = t & 3;               // float4 quarter -> channels q*4..q*4+3
    const int blk = blockIdx.x;
    const int bi  = blk / NCHUNK;
    const int h0  = (blk - bi*NCHUNK) * TH;
    const size_t base = (size_t)bi * PLANE4;
    const float* wx = wxy + ((size_t)bi*2    )*HW;
    const float* wy = wxy + ((size_t)bi*2 + 1)*HW;
    const float4 z = make_float4(0.f,0.f,0.f,0.f);

    float4 bf0=z, bf1=z, bf2=z, bf3=z;   // b centers: bf_k = b(hh-2-k)

    #pragma unroll 1
    for (int hh = h0-3; hh <= h0+TH+4; ++hh) {
        // ---- interval A: publish x row hh (rows h0-3 .. h0+TH+2)
        if (hh <= h0+TH+2) {
            float4 xv = z;
            if (hh >= 0 && hh < HH) {
                if (MODE == MODE_INIT) {
                    const float* src = ae + ((size_t)(bi*DD + q*4)*HH + hh)*WW + w;
                    xv.x = src[0];
                    xv.y = src[HW];
                    xv.z = src[2*HW];
                    xv.w = src[3*(size_t)HW];
                    bt_w[base + (size_t)hh*ROW4 + t] = xv;   // transposed b side-product
                } else {
                    xv = x_in[base + (size_t)hh*ROW4 + t];
                }
            }
            xr[S3SLOT(hh)][t] = xv;
        }
        __syncthreads();

        // ---- interval B
        // S1: x1 = x + ta*(b - A x) at j = hh-1 (rows h0-2 .. h0+TH+1)
        float4 bnew = z;
        {
            const int j = hh - 1;
            if (j >= h0-2 && j <= h0+TH+1) {
                float4 ov = z;
                if (j >= 0 && j < HH) {
                    float4 sc = xr[S3SLOT(j)][t];
                    float4 sl = (w > 0)     ? xr[S3SLOT(j)][t-4] : z;
                    float4 sr = (w < WW-1)  ? xr[S3SLOT(j)][t+4] : z;
                    float4 su = xr[S3SLOT(j-1)][t];
                    float4 sd = xr[S3SLOT(j+1)][t];

                    float wxm, wxp, wym, wyp; LOADW(j);
                    float4 ax; AX4(ax, sc, sl, sr, su, sd);

                    float4 bv;
                    if (MODE == MODE_INIT) bv = sc;   // b == x0
                    else bv = b_in[base + (size_t)j*ROW4 + t];
                    bnew = bv;

                    ov.x = sc.x + ta*(bv.x - ax.x);
                    ov.y = sc.y + ta*(bv.y - ax.y);
                    ov.z = sc.z + ta*(bv.z - ax.z);
                    ov.w = sc.w + ta*(bv.w - ax.w);
                }
                r1[j & 3][t] = ov;
            }
        }

        // S2: x2 = x1 + tb*(b - A x1) at j = hh-3 (rows h0-1 .. h0+TH)
        {
            const int j = hh - 3;
            if (j >= h0-1 && j <= h0+TH) {
                float4 ov = z;
                if (j >= 0 && j < HH) {
                    float4 sc = r1[j & 3][t];
                    float4 sl = (w > 0)     ? r1[j & 3][t-4] : z;
                    float4 sr = (w < WW-1)  ? r1[j & 3][t+4] : z;
                    float4 su = r1[(j-1) & 3][t];
                    float4 sd = r1[(j+1) & 3][t];

                    float wxm, wxp, wym, wyp; LOADW(j);
                    float4 ax; AX4(ax, sc, sl, sr, su, sd);

                    // bf1 = b(hh-3)
                    ov.x = sc.x + tb*(bf1.x - ax.x);
                    ov.y = sc.y + tb*(bf1.y - ax.y);
                    ov.z = sc.z + tb*(bf1.z - ax.z);
                    ov.w = sc.w + tb*(bf1.w - ax.w);
                }
                r2[j & 3][t] = ov;
            }
        }

        // S3: x3 = x2 + tc*(b - A x2) at j = hh-5 (rows h0 .. h0+TH-1)
        {
            const int j = hh - 5;
            if (j >= h0 && j < h0+TH) {
                float4 sc = r2[j & 3][t];
                float4 sl = (w > 0)     ? r2[j & 3][t-4] : z;
                float4 sr = (w < WW-1)  ? r2[j & 3][t+4] : z;
                float4 su = r2[(j-1) & 3][t];
                float4 sd = r2[(j+1) & 3][t];

                float wxm, wxp, wym, wyp; LOADW(j);
                float4 ax; AX4(ax, sc, sl, sr, su, sd);

                float4 on;   // bf3 = b(hh-5)
                on.x = sc.x + tc*(bf3.x - ax.x);
                on.y = sc.y + tc*(bf3.y - ax.y);
                on.z = sc.z + tc*(bf3.z - ax.z);
                on.w = sc.w + tc*(bf3.w - ax.w);

                if (MODE == MODE_LAST) {
                    // direct (B,D,H,W) store: 8-lane runs of consecutive w per
                    // channel -> full 32B sectors.
                    float* o = out_t + ((size_t)(bi*DD + q*4)*HH + j)*WW + w;
                    o[0]              = on.x;
                    o[HW]             = on.y;
                    o[2*HW]           = on.z;
                    o[3*(size_t)HW]   = on.w;
                } else {
                    x_out[base + (size_t)j*ROW4 + t] = on;
                }
            }
        }
        __syncthreads();   // end of epoch: separates ring reads from next S0 write

        // shift b FIFO
        bf3 = bf2; bf2 = bf1; bf1 = bf0; bf0 = bnew;
    }
}

// -------------------- launch --------------------
extern "C" void kernel_launch(void* const* d_in, const int* in_sizes, int n_in,
                              void* d_out, int out_size)
{
    const float* ae  = (const float*)d_in[0];   // (B,D,H,W)
    const float* wxy = (const float*)d_in[1];   // (B,2,H,W)
    float* out = (float*)d_out;                 // (B,D,H,W)

    float4 *bt, *xb;
    cudaGetSymbolAddress((void**)&bt, g_bt);
    cudaGetSymbolAddress((void**)&xb, g_x);
    float4* xA = xb;
    float4* xB = xb + NV4;

    const int SMEM = 11 * ROW4 * (int)sizeof(float4);   // 112640 -> 2 blocks/SM
    cudaFuncSetAttribute(rich_tri<MODE_INIT>, cudaFuncAttributeMaxDynamicSharedMemorySize, SMEM);
    cudaFuncSetAttribute(rich_tri<MODE_MID>,  cudaFuncAttributeMaxDynamicSharedMemorySize, SMEM);
    cudaFuncSetAttribute(rich_tri<MODE_LAST>, cudaFuncAttributeMaxDynamicSharedMemorySize, SMEM);

    // 12 Chebyshev roots on [1,9]: a_k = 5 - 4 cos((2k+1)pi/24), ascending.
    // Large/small paired ordering bounds intermediate amplification.
    double a[12];
    for (int k = 0; k < 12; ++k)
        a[k] = 5.0 - 4.0 * cos((2.0*k + 1.0) * M_PI / 24.0);
    const int ord[12] = {0,11, 1,10, 2,9, 3,8, 4,7, 5,6};
    float tau[12];
    for (int s = 0; s < 12; ++s) tau[s] = (float)(1.0 / a[ord[s]]);

    const int GRID = BB * NCHUNK;   // 256 blocks x 640 threads, 1 wave @ 2/SM

    // L1: x0 = b (from ae, emits bt), apply tau[0..2] -> xA
    rich_tri<MODE_INIT><<<GRID, ROW4, SMEM>>>(nullptr, nullptr, ae, wxy,
                                              xA, bt, nullptr,
                                              tau[0], tau[1], tau[2]);
    // L2: tau[3..5]  xA -> xB
    rich_tri<MODE_MID><<<GRID, ROW4, SMEM>>>(xA, bt, nullptr, wxy,
                                             xB, nullptr, nullptr,
                                             tau[3], tau[4], tau[5]);
    // L3: tau[6..8]  xB -> xA
    rich_tri<MODE_MID><<<GRID, ROW4, SMEM>>>(xB, bt, nullptr, wxy,
                                             xA, nullptr, nullptr,
                                             tau[6], tau[7], tau[8]);
    // L4: tau[9..11] xA -> out (B,D,H,W)
    rich_tri<MODE_LAST><<<GRID, ROW4, SMEM>>>(xA, bt, nullptr, wxy,
                                              nullptr, nullptr, out,
                                              tau[9], tau[10], tau[11]);
}

// round 9
// speedup vs baseline: 1.3727x; 1.1793x over previous
#include <cuda_runtime.h>
#include <math.h>

// Problem constants
#define BB 16
#define DD 16
#define HH 128
#define WW 160
#define ROW4   (WW*4)        // 640 float4 per (b,h) row in (B,H,W,D) layout
#define TH     8             // output rows per block
#define NCHUNK (HH/TH)       // 16
#define PLANE4 (HH*WW*4)
#define NV4    (BB*HH*WW*4)
#define HW     (HH*WW)

#define MODE_INIT 0
#define MODE_MID  1
#define MODE_LAST 2

__device__ float4 g_bt[NV4];      // b in (B,H,W,D) layout
__device__ float4 g_x[2][NV4];    // x ping-pong

extern __shared__ float4 s_mem[];   // xr[4][ROW4] + x1r[4][ROW4]  (80KB)

// -------------------- fused double Richardson step --------------------
// S1: x1 = x  + ta*(b - A x)   at row hh-1   (ring x1r)
// S2: x2 = x1 + tb*(b - A x1)  at row hh-3   (output)
// A z = z + weighted 5-pt Laplacian(z).  One barrier per epoch (R5 scheme).
// Ring audit (mod 4): xr: S0 writes hh, S1 reads hh-2..hh, next-epoch write
// hh+1==hh-3 separated by barrier. x1r: S1 writes hh-1; S2 reads hh-4..hh-2
// (distinct mod 4 from hh-1); next-epoch S1 write of slot (hh)&3 vs this
// epoch's read of row hh-4 (same slot) separated by the barrier.
// b is center-only in both stages -> register FIFO (bf1 = b(hh-3)).
template<int MODE>
__global__ void __launch_bounds__(ROW4, 2)
rich_dbl(const float4* __restrict__ x_in,
         const float4* __restrict__ b_in,
         const float*  __restrict__ ae,
         const float*  __restrict__ wxy,
         float4* __restrict__ x_out,
         float4* __restrict__ bt_w,
         float*  __restrict__ out_t,
         float ta, float tb)
{
    float4 (*xr )[ROW4] = (float4 (*)[ROW4])(s_mem);
    float4 (*x1r)[ROW4] = (float4 (*)[ROW4])(s_mem + 4*ROW4);

    const int t  = threadIdx.x;         // 640
    const int w  = t >> 2;
    const int q  = t & 3;               // float4 quarter -> channels q*4..q*4+3
    const int blk = blockIdx.x;
    const int bi  = blk / NCHUNK;
    const int h0  = (blk - bi*NCHUNK) * TH;
    const size_t base = (size_t)bi * PLANE4;
    const float* wx = wxy + ((size_t)bi*2    )*HW;
    const float* wy = wxy + ((size_t)bi*2 + 1)*HW;
    const float4 z = make_float4(0.f,0.f,0.f,0.f);

    float4 bf0 = z, bf1 = z;     // b centers: bf0 = b(hh-2), bf1 = b(hh-3)

    auto loadx = [&](int hh) -> float4 {
        float4 v = z;
        if (hh >= 0 && hh < HH && hh <= h0+TH+1) {
            if (MODE == MODE_INIT) {
                const float* src = ae + ((size_t)(bi*DD + q*4)*HH + hh)*WW + w;
                v.x = src[0];
                v.y = src[HW];
                v.z = src[2*HW];
                v.w = src[3*(size_t)HW];
            } else {
                v = x_in[base + (size_t)hh*ROW4 + t];
            }
        }
        return v;
    };

    float4 xv = loadx(h0-2);

    #pragma unroll 1
    for (int hh = h0-2; hh <= h0+TH+2; ++hh) {
        // ---- S0: publish x row hh (rows h0-2 .. h0+TH+1), prefetch next
        if (hh <= h0+TH+1) {
            xr[hh & 3][t] = xv;
            if (MODE == MODE_INIT && hh >= 0 && hh < HH)
                bt_w[base + (size_t)hh*ROW4 + t] = xv;   // transposed b side-product
        }
        float4 xnext = loadx(hh+1);
        __syncthreads();

        // ---- S1: x1 = x + ta*(b - A x) at j = hh-1 (rows h0-1 .. h0+TH)
        float4 bnew = z;
        {
            const int j = hh - 1;
            if (j >= h0-1 && j <= h0+TH) {
                float4 ov = z;
                if (j >= 0 && j < HH) {
                    float4 sc = xr[j & 3][t];
                    float4 sl = (w > 0)     ? xr[j & 3][t-4] : z;
                    float4 sr = (w < WW-1)  ? xr[j & 3][t+4] : z;
                    float4 su = xr[(j-1) & 3][t];
                    float4 sd = xr[(j+1) & 3][t];

                    int woff  = j*WW + w;
                    float wxm = (w > 0)     ? wx[woff-1]  : 0.f;
                    float wxp = (w < WW-1)  ? wx[woff]    : 0.f;
                    float wym = (j > 0)     ? wy[woff-WW] : 0.f;
                    float wyp = (j < HH-1)  ? wy[woff]    : 0.f;

                    float4 bv;
                    if (MODE == MODE_INIT) bv = sc;   // b == x0
                    else bv = b_in[base + (size_t)j*ROW4 + t];
                    bnew = bv;

                    float4 ax;
                    ax.x = sc.x + wxm*(sc.x-sl.x) - wxp*(sr.x-sc.x) + wym*(sc.x-su.x) - wyp*(sd.x-sc.x);
                    ax.y = sc.y + wxm*(sc.y-sl.y) - wxp*(sr.y-sc.y) + wym*(sc.y-su.y) - wyp*(sd.y-sc.y);
                    ax.z = sc.z + wxm*(sc.z-sl.z) - wxp*(sr.z-sc.z) + wym*(sc.z-su.z) - wyp*(sd.z-sc.z);
                    ax.w = sc.w + wxm*(sc.w-sl.w) - wxp*(sr.w-sc.w) + wym*(sc.w-su.w) - wyp*(sd.w-sc.w);

                    ov.x = sc.x + ta*(bv.x - ax.x);
                    ov.y = sc.y + ta*(bv.y - ax.y);
                    ov.z = sc.z + ta*(bv.z - ax.z);
                    ov.w = sc.w + ta*(bv.w - ax.w);
                }
                x1r[j & 3][t] = ov;
            }
        }

        // ---- S2: x2 = x1 + tb*(b - A x1) at jc = hh-3 (rows h0 .. h0+TH-1)
        {
            const int jc = hh - 3;
            if (jc >= h0 && jc < h0 + TH) {
                float4 rc = x1r[jc & 3][t];
                float4 rl = (w > 0)     ? x1r[jc & 3][t-4] : z;
                float4 rr = (w < WW-1)  ? x1r[jc & 3][t+4] : z;
                float4 ru = x1r[(jc-1) & 3][t];
                float4 rd = x1r[(jc+1) & 3][t];

                int woff  = jc*WW + w;
                float wxm = (w > 0)     ? wx[woff-1]  : 0.f;
                float wxp = (w < WW-1)  ? wx[woff]    : 0.f;
                float wym = (jc > 0)    ? wy[woff-WW] : 0.f;
                float wyp = (jc < HH-1) ? wy[woff]    : 0.f;

                float4 ar, on;
                ar.x = rc.x + wxm*(rc.x-rl.x) - wxp*(rr.x-rc.x) + wym*(rc.x-ru.x) - wyp*(rd.x-rc.x);
                ar.y = rc.y + wxm*(rc.y-rl.y) - wxp*(rr.y-rc.y) + wym*(rc.y-ru.y) - wyp*(rd.y-rc.y);
                ar.z = rc.z + wxm*(rc.z-rl.z) - wxp*(rr.z-rc.z) + wym*(rc.z-ru.z) - wyp*(rd.z-rc.z);
                ar.w = rc.w + wxm*(rc.w-rl.w) - wxp*(rr.w-rc.w) + wym*(rc.w-ru.w) - wyp*(rd.w-rc.w);

                // bf1 = b(hh-3) from register FIFO
                on.x = rc.x + tb*(bf1.x - ar.x);
                on.y = rc.y + tb*(bf1.y - ar.y);
                on.z = rc.z + tb*(bf1.z - ar.z);
                on.w = rc.w + tb*(bf1.w - ar.w);

                if (MODE == MODE_LAST) {
                    // direct (B,D,H,W) store: 8-lane runs of consecutive w per
                    // channel -> full 32B sectors.
                    float* o = out_t + ((size_t)(bi*DD + q*4)*HH + jc)*WW + w;
                    o[0]              = on.x;
                    o[HW]             = on.y;
                    o[2*HW]           = on.z;
                    o[3*(size_t)HW]   = on.w;
                } else {
                    x_out[base + (size_t)jc*ROW4 + t] = on;
                }
            }
        }

        // FIFO shifts
        bf1 = bf0; bf0 = bnew;
        xv = xnext;
    }
}

// -------------------- launch --------------------
extern "C" void kernel_launch(void* const* d_in, const int* in_sizes, int n_in,
                              void* d_out, int out_size)
{
    const float* ae  = (const float*)d_in[0];   // (B,D,H,W)
    const float* wxy = (const float*)d_in[1];   // (B,2,H,W)
    float* out = (float*)d_out;                 // (B,D,H,W)

    float4 *bt, *xb;
    cudaGetSymbolAddress((void**)&bt, g_bt);
    cudaGetSymbolAddress((void**)&xb, g_x);
    float4* xA = xb;
    float4* xB = xb + NV4;

    const int SMEM = 8 * ROW4 * (int)sizeof(float4);   // 81920 -> 2 blocks/SM
    cudaFuncSetAttribute(rich_dbl<MODE_INIT>, cudaFuncAttributeMaxDynamicSharedMemorySize, SMEM);
    cudaFuncSetAttribute(rich_dbl<MODE_MID>,  cudaFuncAttributeMaxDynamicSharedMemorySize, SMEM);
    cudaFuncSetAttribute(rich_dbl<MODE_LAST>, cudaFuncAttributeMaxDynamicSharedMemorySize, SMEM);

    // 12 Chebyshev roots on [1,9]: a_k = 5 - 4 cos((2k+1)pi/24).
    // Extreme-paired ordering (validated in R8) bounds intermediate growth.
    double a[12];
    for (int k = 0; k < 12; ++k)
        a[k] = 5.0 - 4.0 * cos((2.0*k + 1.0) * M_PI / 24.0);
    const int ord[12] = {0,11, 1,10, 2,9, 3,8, 4,7, 5,6};
    float tau[12];
    for (int s = 0; s < 12; ++s) tau[s] = (float)(1.0 / a[ord[s]]);

    const int GRID = BB * NCHUNK;   // 256 blocks x 640 threads, 1 wave @ 2/SM

    // L1: x0 = b (from ae, emits bt), taus 0,1 -> xA
    rich_dbl<MODE_INIT><<<GRID, ROW4, SMEM>>>(nullptr, nullptr, ae, wxy,
                                              xA, bt, nullptr, tau[0], tau[1]);
    // L2..L5: mid double-steps, ping-pong
    rich_dbl<MODE_MID><<<GRID, ROW4, SMEM>>>(xA, bt, nullptr, wxy,
                                             xB, nullptr, nullptr, tau[2], tau[3]);
    rich_dbl<MODE_MID><<<GRID, ROW4, SMEM>>>(xB, bt, nullptr, wxy,
                                             xA, nullptr, nullptr, tau[4], tau[5]);
    rich_dbl<MODE_MID><<<GRID, ROW4, SMEM>>>(xA, bt, nullptr, wxy,
                                             xB, nullptr, nullptr, tau[6], tau[7]);
    rich_dbl<MODE_MID><<<GRID, ROW4, SMEM>>>(xB, bt, nullptr, wxy,
                                             xA, nullptr, nullptr, tau[8], tau[9]);
    // L6: final double-step straight to out (B,D,H,W)
    rich_dbl<MODE_LAST><<<GRID, ROW4, SMEM>>>(xA, bt, nullptr, wxy,
                                              nullptr, nullptr, out, tau[10], tau[11]);
}

// round 11
// speedup vs baseline: 1.3944x; 1.0158x over previous
#include <cuda_runtime.h>
#include <math.h>

// Problem constants
#define BB 16
#define DD 16
#define HH 128
#define WW 160
#define ROW4   (WW*4)        // 640 float4 per (b,h) row in (B,H,W,D) layout
#define TH     16            // output rows per block
#define NCHUNK (HH/TH)       // 8
#define PLANE4 (HH*WW*4)
#define NV4    (BB*HH*WW*4)
#define HW     (HH*WW)

#define MODE_INIT 0
#define MODE_MID  1
#define MODE_LAST 2

__device__ float4 g_bt[NV4];      // b in (B,H,W,D) layout
__device__ float4 g_x[2][NV4];    // x ping-pong

extern __shared__ float4 s_mem[];   // xr[4][ROW4] + x1r[4][ROW4]  (80KB)

__device__ __forceinline__ float4 shfl_up4(float4 v) {
    float4 o;
    o.x = __shfl_up_sync(0xffffffffu, v.x, 4);
    o.y = __shfl_up_sync(0xffffffffu, v.y, 4);
    o.z = __shfl_up_sync(0xffffffffu, v.z, 4);
    o.w = __shfl_up_sync(0xffffffffu, v.w, 4);
    return o;
}
__device__ __forceinline__ float4 shfl_dn4(float4 v) {
    float4 o;
    o.x = __shfl_down_sync(0xffffffffu, v.x, 4);
    o.y = __shfl_down_sync(0xffffffffu, v.y, 4);
    o.z = __shfl_down_sync(0xffffffffu, v.z, 4);
    o.w = __shfl_down_sync(0xffffffffu, v.w, 4);
    return o;
}

// -------------------- fused double Richardson step --------------------
// S1: x1 = x  + ta*(b - A x)   at row hh-1
// S2: x2 = x1 + tb*(b - A x1)  at row hh-3   (output)
// Vertical stencil neighbors come from per-thread register FIFOs (own column);
// horizontal neighbors via warp shuffle (t+-4 in-warp for lanes 4..27), edge
// lanes read the smem rings. Ring WRITES identical to the R9 kernel, so the
// mod-4 slot-collision audit is unchanged. Row-validity tests are warp-uniform.
// FIFO timeline (PRE-shift, during epoch hh):
//   xm1 = x(hh-1), xm2 = x(hh-2), xv = x(hh)
//   y0  = x1(hh-2), y1 = x1(hh-3), y2 = x1(hh-4)
//   bf0 = b(hh-2),  bf1 = b(hh-3)
// S2 at jc = hh-3 uses c = y1 (= x1(jc)), u = y2 (= x1(jc-1)), d = y0 (= x1(jc+1)).
template<int MODE>
__global__ void __launch_bounds__(ROW4, 1)
rich_dbl(const float4* __restrict__ x_in,
         const float4* __restrict__ b_in,
         const float*  __restrict__ ae,
         const float*  __restrict__ wxy,
         float4* __restrict__ x_out,
         float4* __restrict__ bt_w,
         float*  __restrict__ out_t,
         float ta, float tb)
{
    float4 (*xr )[ROW4] = (float4 (*)[ROW4])(s_mem);
    float4 (*x1r)[ROW4] = (float4 (*)[ROW4])(s_mem + 4*ROW4);

    const int t    = threadIdx.x;       // 640
    const int lane = t & 31;
    const int w    = t >> 2;
    const int q    = t & 3;             // float4 quarter -> channels q*4..q*4+3
    const int blk  = blockIdx.x;
    const int bi   = blk / NCHUNK;
    const int h0   = (blk - bi*NCHUNK) * TH;
    const size_t base = (size_t)bi * PLANE4;
    const float* wx = wxy + ((size_t)bi*2    )*HW;
    const float* wy = wxy + ((size_t)bi*2 + 1)*HW;
    const float4 z = make_float4(0.f,0.f,0.f,0.f);

    auto loadx = [&](int hh) -> float4 {
        float4 v = z;
        if (hh >= 0 && hh < HH && hh <= h0+TH+1) {
            if (MODE == MODE_INIT) {
                const float* src = ae + ((size_t)(bi*DD + q*4)*HH + hh)*WW + w;
                v.x = src[0];
                v.y = src[HW];
                v.z = src[2*HW];
                v.w = src[3*(size_t)HW];
            } else {
                v = x_in[base + (size_t)hh*ROW4 + t];
            }
        }
        return v;
    };

    // register FIFOs (per-thread center columns) -- see timeline above
    float4 xm2 = z, xm1 = z;
    float4 y0 = z, y1 = z, y2 = z;
    float4 bf0 = z, bf1 = z;

    float4 xv = loadx(h0-2);            // x(hh) at loop entry

    #pragma unroll 1
    for (int hh = h0-2; hh <= h0+TH+2; ++hh) {
        // ---- S0: publish x row hh (edge-lane service), prefetch next
        if (hh <= h0+TH+1) {
            xr[hh & 3][t] = xv;
            if (MODE == MODE_INIT && hh >= 0 && hh < HH)
                bt_w[base + (size_t)hh*ROW4 + t] = xv;   // transposed b side-product
        }
        float4 xnext = loadx(hh+1);
        __syncthreads();

        // ---- S1: x1 = x + ta*(b - A x) at j = hh-1 (rows h0-1 .. h0+TH)
        float4 ov = z, bnew = z;
        {
            const int j = hh - 1;
            if (j >= h0-1 && j <= h0+TH && j >= 0 && j < HH) {   // warp-uniform
                float4 c = xm1, u = xm2, d = xv;
                float4 l = shfl_up4(c);
                float4 r = shfl_dn4(c);
                if (lane < 4)   l = (w > 0)    ? xr[j & 3][t-4] : z;
                if (lane >= 28) r = (w < WW-1) ? xr[j & 3][t+4] : z;

                int woff  = j*WW + w;
                float wxm = (w > 0)     ? wx[woff-1]  : 0.f;
                float wxp = (w < WW-1)  ? wx[woff]    : 0.f;
                float wym = (j > 0)     ? wy[woff-WW] : 0.f;
                float wyp = (j < HH-1)  ? wy[woff]    : 0.f;

                float4 bv;
                if (MODE == MODE_INIT) bv = c;   // b == x0
                else bv = b_in[base + (size_t)j*ROW4 + t];
                bnew = bv;

                float4 ax;
                ax.x = c.x + wxm*(c.x-l.x) - wxp*(r.x-c.x) + wym*(c.x-u.x) - wyp*(d.x-c.x);
                ax.y = c.y + wxm*(c.y-l.y) - wxp*(r.y-c.y) + wym*(c.y-u.y) - wyp*(d.y-c.y);
                ax.z = c.z + wxm*(c.z-l.z) - wxp*(r.z-c.z) + wym*(c.z-u.z) - wyp*(d.z-c.z);
                ax.w = c.w + wxm*(c.w-l.w) - wxp*(r.w-c.w) + wym*(c.w-u.w) - wyp*(d.w-c.w);

                ov.x = c.x + ta*(bv.x - ax.x);
                ov.y = c.y + ta*(bv.y - ax.y);
                ov.z = c.z + ta*(bv.z - ax.z);
                ov.w = c.w + ta*(bv.w - ax.w);
            }
            if (j >= h0-1 && j <= h0+TH)
                x1r[j & 3][t] = ov;      // ring write (edge-lane service)
        }

        // ---- S2: x2 = x1 + tb*(b - A x1) at jc = hh-3 (rows h0 .. h0+TH-1)
        {
            const int jc = hh - 3;
            if (jc >= h0 && jc < h0 + TH) {      // warp-uniform
                // PRE-shift FIFO: c = x1(jc) = y1, u = x1(jc-1) = y2, d = x1(jc+1) = y0
                float4 c = y1, u = y2, d = y0;
                float4 l = shfl_up4(c);
                float4 r = shfl_dn4(c);
                if (lane < 4)   l = (w > 0)    ? x1r[jc & 3][t-4] : z;
                if (lane >= 28) r = (w < WW-1) ? x1r[jc & 3][t+4] : z;

                int woff  = jc*WW + w;
                float wxm = (w > 0)     ? wx[woff-1]  : 0.f;
                float wxp = (w < WW-1)  ? wx[woff]    : 0.f;
                float wym = (jc > 0)    ? wy[woff-WW] : 0.f;
                float wyp = (jc < HH-1) ? wy[woff]    : 0.f;

                float4 ar, on;
                ar.x = c.x + wxm*(c.x-l.x) - wxp*(r.x-c.x) + wym*(c.x-u.x) - wyp*(d.x-c.x);
                ar.y = c.y + wxm*(c.y-l.y) - wxp*(r.y-c.y) + wym*(c.y-u.y) - wyp*(d.y-c.y);
                ar.z = c.z + wxm*(c.z-l.z) - wxp*(r.z-c.z) + wym*(c.z-u.z) - wyp*(d.z-c.z);
                ar.w = c.w + wxm*(c.w-l.w) - wxp*(r.w-c.w) + wym*(c.w-u.w) - wyp*(d.w-c.w);

                // bf1 = b(hh-3) = b(jc)
                on.x = c.x + tb*(bf1.x - ar.x);
                on.y = c.y + tb*(bf1.y - ar.y);
                on.z = c.z + tb*(bf1.z - ar.z);
                on.w = c.w + tb*(bf1.w - ar.w);

                if (MODE == MODE_LAST) {
                    // direct (B,D,H,W) store: 8-lane runs of consecutive w per
                    // channel -> full 32B sectors.
                    float* o = out_t + ((size_t)(bi*DD + q*4)*HH + jc)*WW + w;
                    o[0]              = on.x;
                    o[HW]             = on.y;
                    o[2*HW]           = on.z;
                    o[3*(size_t)HW]   = on.w;
                } else {
                    x_out[base + (size_t)jc*ROW4 + t] = on;
                }
            }
        }

        // ---- FIFO shifts (end of epoch)
        y2 = y1; y1 = y0; y0 = ov;
        bf1 = bf0; bf0 = bnew;
        xm2 = xm1; xm1 = xv; xv = xnext;
    }
}

// -------------------- launch --------------------
extern "C" void kernel_launch(void* const* d_in, const int* in_sizes, int n_in,
                              void* d_out, int out_size)
{
    const float* ae  = (const float*)d_in[0];   // (B,D,H,W)
    const float* wxy = (const float*)d_in[1];   // (B,2,H,W)
    float* out = (float*)d_out;                 // (B,D,H,W)

    float4 *bt, *xb;
    cudaGetSymbolAddress((void**)&bt, g_bt);
    cudaGetSymbolAddress((void**)&xb, g_x);
    float4* xA = xb;
    float4* xB = xb + NV4;

    const int SMEM = 8 * ROW4 * (int)sizeof(float4);   // 81920
    cudaFuncSetAttribute(rich_dbl<MODE_INIT>, cudaFuncAttributeMaxDynamicSharedMemorySize, SMEM);
    cudaFuncSetAttribute(rich_dbl<MODE_MID>,  cudaFuncAttributeMaxDynamicSharedMemorySize, SMEM);
    cudaFuncSetAttribute(rich_dbl<MODE_LAST>, cudaFuncAttributeMaxDynamicSharedMemorySize, SMEM);

    // 12 Chebyshev roots on [1,9]: a_k = 5 - 4 cos((2k+1)pi/24).
    // Extreme-paired ordering (validated R8/R9) bounds intermediate growth.
    double a[12];
    for (int k = 0; k < 12; ++k)
        a[k] = 5.0 - 4.0 * cos((2.0*k + 1.0) * M_PI / 24.0);
    const int ord[12] = {0,11, 1,10, 2,9, 3,8, 4,7, 5,6};
    float tau[12];
    for (int s = 0; s < 12; ++s) tau[s] = (float)(1.0 / a[ord[s]]);

    const int GRID = BB * NCHUNK;   // 128 blocks x 640 threads -> 1 block/SM, balanced

    // L1: x0 = b (from ae, emits bt), taus 0,1 -> xA
    rich_dbl<MODE_INIT><<<GRID, ROW4, SMEM>>>(nullptr, nullptr, ae, wxy,
                                              xA, bt, nullptr, tau[0], tau[1]);
    // L2..L5: mid double-steps, ping-pong
    rich_dbl<MODE_MID><<<GRID, ROW4, SMEM>>>(xA, bt, nullptr, wxy,
                                             xB, nullptr, nullptr, tau[2], tau[3]);
    rich_dbl<MODE_MID><<<GRID, ROW4, SMEM>>>(xB, bt, nullptr, wxy,
                                             xA, nullptr, nullptr, tau[4], tau[5]);
    rich_dbl<MODE_MID><<<GRID, ROW4, SMEM>>>(xA, bt, nullptr, wxy,
                                             xB, nullptr, nullptr, tau[6], tau[7]);
    rich_dbl<MODE_MID><<<GRID, ROW4, SMEM>>>(xB, bt, nullptr, wxy,
                                             xA, nullptr, nullptr, tau[8], tau[9]);
    // L6: final double-step straight to out (B,D,H,W)
    rich_dbl<MODE_LAST><<<GRID, ROW4, SMEM>>>(xA, bt, nullptr, wxy,
                                              nullptr, nullptr, out, tau[10], tau[11]);
}

// round 12
// speedup vs baseline: 1.7329x; 1.2427x over previous
#include <cuda_runtime.h>
#include <math.h>

// Problem constants
#define BB 16
#define DD 16
#define HH 128
#define WW 160
#define W4 (WW/4)            // 40 float4 per (image,channel,row)
#define NT (DD*W4)           // 640 threads = 16 ch x 40 float4-cols
#define TH 16                // output rows per block
#define NCHUNK (HH/TH)       // 8
#define HW (HH*WW)
#define PL4 (HH*W4)          // float4 per channel plane
#define NV4 (BB*DD*PL4)

__device__ float4 g_x[2][NV4];    // x ping-pong, native (B,D,H,W) layout

__device__ __forceinline__ int clampr(int r) {
    return r < 0 ? 0 : (r > HH-1 ? HH-1 : r);
}

// -------------------- fused double Richardson step, w-vectorized ----------
// S1: x1 = x  + ta*(b - A x)   at row e-1
// S2: x2 = x1 + tb*(b - A x1)  at row e-3  (stored)
// Thread t = ch*40 + wb holds x[bi][ch][row][4*wb .. 4*wb+3].
// Horizontal neighbors: in-register shifts; the two boundary scalars
// (x[w-1], x[w+4]) via per-row smem edge rings (lo=.x, hi=.w), depth 4.
// Vertical neighbors: per-thread register FIFOs (R11-corrected timeline):
//   epoch e body: xm1=x(e-1), xm2=x(e-2), xv=x(e);
//                 y0=x1(e-2), y1=x1(e-3), y2=x1(e-4); bf1=b(e-3).
// Ring audit (interval after bar(e)): writes xlo/xhi[(e+1)&3] (S0 of e+1) vs
// read [(e-1)&3] differ 2; writes ylo/yhi[(e-1)&3] vs read [(e-3)&3] differ 2.
// Boundary weights zeroed exactly per reference padding (wb==0 / wb==39 /
// j==0 / j==HH-1); all out-of-range rows are clamped loads whose
// contributions are multiplied by those zeros.
__global__ void __launch_bounds__(NT, 1)
rich_dbl(const float4* __restrict__ x_in,
         const float4* __restrict__ b_in,
         const float*  __restrict__ wxy,
         float4* __restrict__ x_out,
         int same_xb, float ta, float tb)
{
    __shared__ float xlo[4][NT], xhi[4][NT];
    __shared__ float ylo[4][NT], yhi[4][NT];

    const int t  = threadIdx.x;        // 640
    const int ch = t / W4;
    const int wb = t - ch*W4;
    const int blk = blockIdx.x;
    const int bi  = blk / NCHUNK;
    const int h0  = (blk - bi*NCHUNK) * TH;

    const size_t cb = ((size_t)(bi*DD + ch))*PL4 + wb;   // float4 column base
    const float* wxb = wxy + (size_t)bi*2*HW + wb*4;     // wx row base (+w0)
    const float* wyb = wxb + HW;                          // wy row base (+w0)
    const int tm = t > 0 ? t-1 : 0;
    const int tp = t < NT-1 ? t+1 : NT-1;
    const float4 z = {0.f,0.f,0.f,0.f};

    // one Richardson stage at row j: o = c + tau*(b - (c + lap(c,u,d,lw,rx)))
    auto stage = [&](int j, float4 c, float4 u, float4 d,
                     float lw, float rx, float4 bv, float tau) -> float4 {
        const int jc = clampr(j);
        const float* wxr = wxb + jc*WW;
        float4 wxv = *(const float4*)wxr;
        float  wxl = (wb > 0) ? wxr[-1] : 0.f;        // wx[w0-1]; 0 at w==0
        if (wb == W4-1) wxv.w = 0.f;                   // no hx at w==WW-1
        float4 wyd = *(const float4*)(wyb + jc*WW);
        float4 wyu = *(const float4*)(wyb + clampr(j-1)*WW);
        if (j <= 0)     wyu = z;                       // no hy above row 0
        if (j >= HH-1)  wyd = z;                       // no hy below row HH-1

        float hxm = wxl   * (c.x - lw);
        float hx0 = wxv.x * (c.y - c.x);
        float hx1 = wxv.y * (c.z - c.y);
        float hx2 = wxv.z * (c.w - c.z);
        float hx3 = wxv.w * (rx  - c.w);

        float4 lap;
        lap.x = (hxm - hx0) + wyu.x*(c.x - u.x) - wyd.x*(d.x - c.x);
        lap.y = (hx0 - hx1) + wyu.y*(c.y - u.y) - wyd.y*(d.y - c.y);
        lap.z = (hx1 - hx2) + wyu.z*(c.z - u.z) - wyd.z*(d.z - c.z);
        lap.w = (hx2 - hx3) + wyu.w*(c.w - u.w) - wyd.w*(d.w - c.w);

        float4 o;
        o.x = c.x + tau*(bv.x - c.x - lap.x);
        o.y = c.y + tau*(bv.y - c.y - lap.y);
        o.z = c.z + tau*(bv.z - c.z - lap.z);
        o.w = c.w + tau*(bv.w - c.w - lap.w);
        return o;
    };

    // register FIFOs
    float4 xm2 = z, xm1 = z;
    float4 y0 = z, y1 = z, y2 = z;
    float4 bf0 = z, bf1 = z;

    float4 xv = x_in[cb + (size_t)clampr(h0-2)*W4];

    #pragma unroll 1
    for (int e = h0-2; e <= h0+TH+2; ++e) {
        // ---- S0: publish edge scalars of x row e; prefetch row e+1
        xlo[e & 3][t] = xv.x;
        xhi[e & 3][t] = xv.w;
        float4 xnext = x_in[cb + (size_t)clampr(e+1)*W4];
        __syncthreads();

        // ---- S1: row j = e-1  (active for x1 rows h0-1 .. h0+TH)
        float4 ov = z, bnew = z;
        if (e >= h0 && e <= h0+TH+1) {
            const int j = e - 1;
            float lw = xhi[j & 3][tm];
            float rx = xlo[j & 3][tp];
            float4 bv;
            if (same_xb) bv = xm1;                      // b == x0
            else bv = b_in[cb + (size_t)clampr(j)*W4];
            bnew = bv;
            ov = stage(j, xm1, xm2, xv, lw, rx, bv, ta);
            ylo[j & 3][t] = ov.x;
            yhi[j & 3][t] = ov.w;
        }

        // ---- S2: row j2 = e-3  (outputs h0 .. h0+TH-1, always in-range)
        if (e >= h0+3) {
            const int j2 = e - 3;
            float lw = yhi[j2 & 3][tm];
            float rx = ylo[j2 & 3][tp];
            float4 on = stage(j2, y1, y2, y0, lw, rx, bf1, tb);
            x_out[cb + (size_t)j2*W4] = on;
        }

        // ---- FIFO shifts (end of epoch)
        y2 = y1; y1 = y0; y0 = ov;
        bf1 = bf0; bf0 = bnew;
        xm2 = xm1; xm1 = xv; xv = xnext;
    }
}

// -------------------- launch --------------------
extern "C" void kernel_launch(void* const* d_in, const int* in_sizes, int n_in,
                              void* d_out, int out_size)
{
    const float4* ae  = (const float4*)d_in[0];   // (B,D,H,W) fp32
    const float*  wxy = (const float*)d_in[1];    // (B,2,H,W)
    float4* out = (float4*)d_out;                 // (B,D,H,W)

    float4* xb;
    cudaGetSymbolAddress((void**)&xb, g_x);
    float4* xA = xb;
    float4* xB = xb + NV4;

    // 12 Chebyshev roots on [1,9]: a_k = 5 - 4 cos((2k+1)pi/24).
    // Extreme-paired ordering (validated R8/R9/R11).
    double a[12];
    for (int k = 0; k < 12; ++k)
        a[k] = 5.0 - 4.0 * cos((2.0*k + 1.0) * M_PI / 24.0);
    const int ord[12] = {0,11, 1,10, 2,9, 3,8, 4,7, 5,6};
    float tau[12];
    for (int s = 0; s < 12; ++s) tau[s] = (float)(1.0 / a[ord[s]]);

    const int GRID = BB * NCHUNK;   // 128 blocks x 640 threads

    // b == ae in every launch; L1 additionally has x_in == ae (same_xb=1).
    rich_dbl<<<GRID, NT>>>(ae, ae, wxy, xA, 1, tau[0],  tau[1]);
    rich_dbl<<<GRID, NT>>>(xA, ae, wxy, xB, 0, tau[2],  tau[3]);
    rich_dbl<<<GRID, NT>>>(xB, ae, wxy, xA, 0, tau[4],  tau[5]);
    rich_dbl<<<GRID, NT>>>(xA, ae, wxy, xB, 0, tau[6],  tau[7]);
    rich_dbl<<<GRID, NT>>>(xB, ae, wxy, xA, 0, tau[8],  tau[9]);
    rich_dbl<<<GRID, NT>>>(xA, ae, wxy, out, 0, tau[10], tau[11]);
}

// round 13
// speedup vs baseline: 1.8005x; 1.0390x over previous
#include <cuda_runtime.h>
#include <math.h>

// Problem constants
#define BB 16
#define DD 16
#define HH 128
#define WW 160
#define W4 (WW/4)            // 40 float4 per (image,channel,row)
#define NT (DD*W4)           // 640 threads = 16 ch x 40 float4-cols
#define TH 16                // output rows per block
#define NCHUNK (HH/TH)       // 8
#define HW (HH*WW)
#define PL4 (HH*W4)          // float4 per channel plane
#define NV4 (BB*DD*PL4)

__device__ float4 g_x[2][NV4];    // x ping-pong, native (B,D,H,W) layout

__device__ __forceinline__ int clampr(int r) {
    return r < 0 ? 0 : (r > HH-1 ? HH-1 : r);
}

extern __shared__ float s_edge[];   // 6 arrays [4][NT]: xlo,xhi,ylo,yhi,plo,phi

// -------------------- fused TRIPLE Richardson step, w-vectorized ----------
// S1: x1 = x  + ta*(b - A x)   at row e-1
// S2: x2 = x1 + tb*(b - A x1)  at row e-3
// S3: x3 = x2 + tc*(b - A x2)  at row e-5  (stored)
// Thread t = ch*40 + wb holds [bi][ch][row][4*wb..4*wb+3].
// Horizontal: in-register; the 2 boundary scalars per stage via smem edge
// rings, depth 4.  Vertical: per-thread register FIFOs.
// FIFO timeline (PRE-shift, during epoch e):
//   xm1=x(e-1) xm2=x(e-2) xv=x(e)
//   y0=x1(e-2) y1=x1(e-3) y2=x1(e-4)
//   z0=x2(e-4) z1=x2(e-5) z2=x2(e-6)
//   bf0=b(e-2) bf1=b(e-3);  S3 reloads b(e-5) from L1/L2.
// Ring audit (interval between bars, writes vs reads, mod 4):
//   x: S0(e+1) writes (e+1)&3 vs S1(e) reads (e-1)&3  -> differ 2
//   y: S1(e)  writes (e-1)&3 vs S2(e) reads (e-3)&3  -> differ 2
//   p: S2(e)  writes (e-3)&3 vs S3(e) reads (e-5)&3  -> differ 2
// Pseudo-rows (outside [0,HH)) feed consumers only through weights the
// reference's padding makes zero (wyu at row<=0, wyd at row>=HH-1,
// wx at w edges).
__global__ void __launch_bounds__(NT, 1)
rich_tri(const float4* __restrict__ x_in,
         const float4* __restrict__ b_in,
         const float*  __restrict__ wxy,
         float4* __restrict__ x_out,
         int same_xb, float ta, float tb, float tc)
{
    float (*xlo)[NT] = (float (*)[NT])(s_edge);
    float (*xhi)[NT] = (float (*)[NT])(s_edge + 4*NT);
    float (*ylo)[NT] = (float (*)[NT])(s_edge + 8*NT);
    float (*yhi)[NT] = (float (*)[NT])(s_edge + 12*NT);
    float (*plo)[NT] = (float (*)[NT])(s_edge + 16*NT);
    float (*phi)[NT] = (float (*)[NT])(s_edge + 20*NT);

    const int t  = threadIdx.x;        // 640
    const int ch = t / W4;
    const int wb = t - ch*W4;
    const int blk = blockIdx.x;
    const int bi  = blk / NCHUNK;
    const int h0  = (blk - bi*NCHUNK) * TH;

    const size_t cb = ((size_t)(bi*DD + ch))*PL4 + wb;   // float4 column base
    const float* wxb = wxy + (size_t)bi*2*HW + wb*4;     // wx row base (+w0)
    const float* wyb = wxb + HW;                          // wy row base (+w0)
    const int tm = t > 0 ? t-1 : 0;
    const int tp = t < NT-1 ? t+1 : NT-1;
    const float4 z = {0.f,0.f,0.f,0.f};

    // one Richardson stage at row j: o = c + tau*(b - (c + lap))
    auto stage = [&](int j, float4 c, float4 u, float4 d,
                     float lw, float rx, float4 bv, float tau) -> float4 {
        const int jc = clampr(j);
        const float* wxr = wxb + jc*WW;
        float4 wxv = *(const float4*)wxr;
        float  wxl = (wb > 0) ? wxr[-1] : 0.f;
        if (wb == W4-1) wxv.w = 0.f;
        float4 wyd = *(const float4*)(wyb + jc*WW);
        float4 wyu = *(const float4*)(wyb + clampr(j-1)*WW);
        if (j <= 0)     wyu = z;
        if (j >= HH-1)  wyd = z;

        float hxm = wxl   * (c.x - lw);
        float hx0 = wxv.x * (c.y - c.x);
        float hx1 = wxv.y * (c.z - c.y);
        float hx2 = wxv.z * (c.w - c.z);
        float hx3 = wxv.w * (rx  - c.w);

        float4 lap;
        lap.x = (hxm - hx0) + wyu.x*(c.x - u.x) - wyd.x*(d.x - c.x);
        lap.y = (hx0 - hx1) + wyu.y*(c.y - u.y) - wyd.y*(d.y - c.y);
        lap.z = (hx1 - hx2) + wyu.z*(c.z - u.z) - wyd.z*(d.z - c.z);
        lap.w = (hx2 - hx3) + wyu.w*(c.w - u.w) - wyd.w*(d.w - c.w);

        float4 o;
        o.x = c.x + tau*(bv.x - c.x - lap.x);
        o.y = c.y + tau*(bv.y - c.y - lap.y);
        o.z = c.z + tau*(bv.z - c.z - lap.z);
        o.w = c.w + tau*(bv.w - c.w - lap.w);
        return o;
    };

    // register FIFOs
    float4 xm2 = z, xm1 = z;
    float4 y0 = z, y1 = z, y2 = z;
    float4 z0 = z, z1 = z, z2 = z;
    float4 bf0 = z, bf1 = z;

    float4 xv = x_in[cb + (size_t)clampr(h0-3)*W4];

    #pragma unroll 1
    for (int e = h0-3; e <= h0+TH+4; ++e) {
        // ---- S0: publish edge scalars of x row e; prefetch row e+1
        if (e <= h0+TH+2) {
            xlo[e & 3][t] = xv.x;
            xhi[e & 3][t] = xv.w;
        }
        float4 xnext = x_in[cb + (size_t)clampr(e+1)*W4];
        __syncthreads();

        // ---- S1: row j1 = e-1, active j1 in [h0-2, h0+TH+1]
        float4 ov = z, bnew = z;
        if (e >= h0-1 && e <= h0+TH+2) {
            const int j1 = e - 1;
            float lw = xhi[j1 & 3][tm];
            float rx = xlo[j1 & 3][tp];
            float4 bv;
            if (same_xb) bv = xm1;                      // b == x0
            else bv = b_in[cb + (size_t)clampr(j1)*W4];
            bnew = bv;
            ov = stage(j1, xm1, xm2, xv, lw, rx, bv, ta);
            ylo[j1 & 3][t] = ov.x;
            yhi[j1 & 3][t] = ov.w;
        }

        // ---- S2: row j2 = e-3, active j2 in [h0-1, h0+TH]
        float4 pv = z;
        if (e >= h0+2 && e <= h0+TH+3) {
            const int j2 = e - 3;
            float lw = yhi[j2 & 3][tm];
            float rx = ylo[j2 & 3][tp];
            pv = stage(j2, y1, y2, y0, lw, rx, bf1, tb);
            plo[j2 & 3][t] = pv.x;
            phi[j2 & 3][t] = pv.w;
        }

        // ---- S3: row j3 = e-5, outputs h0 .. h0+TH-1 (always real rows)
        if (e >= h0+5) {
            const int j3 = e - 5;
            float lw = phi[j3 & 3][tm];
            float rx = plo[j3 & 3][tp];
            float4 bv = b_in[cb + (size_t)j3*W4];       // L1-resident reload
            float4 on = stage(j3, z1, z2, z0, lw, rx, bv, tc);
            x_out[cb + (size_t)j3*W4] = on;
        }

        // ---- FIFO shifts (end of epoch)
        z2 = z1; z1 = z0; z0 = pv;
        y2 = y1; y1 = y0; y0 = ov;
        bf1 = bf0; bf0 = bnew;
        xm2 = xm1; xm1 = xv; xv = xnext;
    }
}

// -------------------- launch --------------------
extern "C" void kernel_launch(void* const* d_in, const int* in_sizes, int n_in,
                              void* d_out, int out_size)
{
    const float4* ae  = (const float4*)d_in[0];   // (B,D,H,W) fp32
    const float*  wxy = (const float*)d_in[1];    // (B,2,H,W)
    float4* out = (float4*)d_out;                 // (B,D,H,W)

    float4* xb;
    cudaGetSymbolAddress((void**)&xb, g_x);
    float4* xA = xb;
    float4* xB = xb + NV4;

    const int SMEM = 24 * NT * (int)sizeof(float);   // 61440
    cudaFuncSetAttribute(rich_tri, cudaFuncAttributeMaxDynamicSharedMemorySize, SMEM);

    // 12 Chebyshev roots on [1,9]: a_k = 5 - 4 cos((2k+1)pi/24).
    // Same extreme-paired sequence as R8..R12 (identical arithmetic order,
    // just regrouped 3 per launch).
    double a[12];
    for (int k = 0; k < 12; ++k)
        a[k] = 5.0 - 4.0 * cos((2.0*k + 1.0) * M_PI / 24.0);
    const int ord[12] = {0,11, 1,10, 2,9, 3,8, 4,7, 5,6};
    float tau[12];
    for (int s = 0; s < 12; ++s) tau[s] = (float)(1.0 / a[ord[s]]);

    const int GRID = BB * NCHUNK;   // 128 blocks x 640 threads, 1/SM, balanced

    rich_tri<<<GRID, NT, SMEM>>>(ae, ae, wxy, xA, 1, tau[0], tau[1], tau[2]);
    rich_tri<<<GRID, NT, SMEM>>>(xA, ae, wxy, xB, 0, tau[3], tau[4], tau[5]);
    rich_tri<<<GRID, NT, SMEM>>>(xB, ae, wxy, xA, 0, tau[6], tau[7], tau[8]);
    rich_tri<<<GRID, NT, SMEM>>>(xA, ae, wxy, out, 0, tau[9], tau[10], tau[11]);
}

// round 14
// speedup vs baseline: 1.8689x; 1.0380x over previous
#include <cuda_runtime.h>
#include <math.h>

// Problem constants
#define BB 16
#define DD 16
#define HH 128
#define WW 160
#define W4 (WW/4)            // 40 float4 per (image,channel,row)
#define NCH 8                // channels per block
#define NT (NCH*W4)          // 320 threads
#define TH 16                // output rows per block
#define NCHUNK (HH/TH)       // 8
#define HW (HH*WW)
#define PL4 (HH*W4)          // float4 per channel plane
#define NV4 (BB*DD*PL4)

__device__ float4 g_x[2][NV4];    // x ping-pong, native (B,D,H,W) layout

__device__ __forceinline__ int clampr(int r) {
    return r < 0 ? 0 : (r > HH-1 ? HH-1 : r);
}

// -------------------- fused TRIPLE Richardson step, w-vectorized ----------
// S1: x1 = x  + ta*(b - A x)   at row e-1
// S2: x2 = x1 + tb*(b - A x1)  at row e-3
// S3: x3 = x2 + tc*(b - A x2)  at row e-5  (stored)
// Thread t = ch*40 + wb holds [bi][cg*8+ch][row][4*wb..4*wb+3].
// Horizontal: in-register; 2 boundary scalars per stage via smem edge rings
// (depth 4). Vertical: per-thread register FIFOs (R11/R13 timeline):
//   epoch e: xm1=x(e-1) xm2=x(e-2) xv=x(e); y*=x1(e-2..e-4); z*=x2(e-4..e-6);
//   bf1=b(e-3); S3 reloads b(e-5) (L1-resident).
// Ring audit identical to R13 (write/read slots differ by 2 mod 4).
// Channel-boundary garbage at t+-1 is multiplied by exact-zero wx edge
// weights (reference padding). Epoch loop unrolled x4 (24 iters): FIFO
// shifts become register renames; (h0-3+i)&3 folds per unrolled lane
// (h0 = chunk<<4).
template<int SAME_XB>
__global__ void __launch_bounds__(NT, 2)
rich_tri(const float4* __restrict__ x_in,
         const float4* __restrict__ b_in,
         const float*  __restrict__ wxy,
         float4* __restrict__ x_out,
         float ta, float tb, float tc)
{
    __shared__ float xlo[4][NT], xhi[4][NT];
    __shared__ float ylo[4][NT], yhi[4][NT];
    __shared__ float plo[4][NT], phi[4][NT];

    const int t  = threadIdx.x;        // 320
    const int ch = t / W4;             // 0..7
    const int wb = t - ch*W4;
    const int blk = blockIdx.x;
    const int cg  = blk & 1;           // channel group
    const int r2  = blk >> 1;
    const int bi  = r2 / NCHUNK;
    const int h0  = (r2 - bi*NCHUNK) << 4;   // chunk*TH, low 4 bits zero

    const size_t cb = ((size_t)(bi*DD + cg*NCH + ch))*PL4 + wb;
    const float* wxb = wxy + (size_t)bi*2*HW + wb*4;
    const float* wyb = wxb + HW;
    const int tm = t > 0 ? t-1 : 0;
    const int tp = t < NT-1 ? t+1 : NT-1;
    const float4 z = {0.f,0.f,0.f,0.f};

    // one Richardson stage at row j: o = c + tau*(b - (c + lap))
    auto stage = [&](int j, float4 c, float4 u, float4 d,
                     float lw, float rx, float4 bv, float tau) -> float4 {
        const int jc = clampr(j);
        const float* wxr = wxb + jc*WW;
        float4 wxv = *(const float4*)wxr;
        float  wxl = (wb > 0) ? wxr[-1] : 0.f;
        if (wb == W4-1) wxv.w = 0.f;
        float4 wyd = *(const float4*)(wyb + jc*WW);
        float4 wyu = *(const float4*)(wyb + clampr(j-1)*WW);
        if (j <= 0)     wyu = z;
        if (j >= HH-1)  wyd = z;

        float hxm = wxl   * (c.x - lw);
        float hx0 = wxv.x * (c.y - c.x);
        float hx1 = wxv.y * (c.z - c.y);
        float hx2 = wxv.z * (c.w - c.z);
        float hx3 = wxv.w * (rx  - c.w);

        float4 lap;
        lap.x = (hxm - hx0) + wyu.x*(c.x - u.x) - wyd.x*(d.x - c.x);
        lap.y = (hx0 - hx1) + wyu.y*(c.y - u.y) - wyd.y*(d.y - c.y);
        lap.z = (hx1 - hx2) + wyu.z*(c.z - u.z) - wyd.z*(d.z - c.z);
        lap.w = (hx2 - hx3) + wyu.w*(c.w - u.w) - wyd.w*(d.w - c.w);

        float4 o;
        o.x = c.x + tau*(bv.x - c.x - lap.x);
        o.y = c.y + tau*(bv.y - c.y - lap.y);
        o.z = c.z + tau*(bv.z - c.z - lap.z);
        o.w = c.w + tau*(bv.w - c.w - lap.w);
        return o;
    };

    // register FIFOs
    float4 xm2 = z, xm1 = z;
    float4 y0 = z, y1 = z, y2 = z;
    float4 z0 = z, z1 = z, z2 = z;
    float4 bf0 = z, bf1 = z;

    float4 xv = x_in[cb + (size_t)clampr(h0-3)*W4];

    #pragma unroll 4
    for (int i = 0; i < TH+8; ++i) {           // e = h0-3 .. h0+TH+4
        const int e = h0 - 3 + i;

        // ---- S0: publish edge scalars of x row e; prefetch row e+1
        if (e <= h0+TH+2) {
            xlo[e & 3][t] = xv.x;
            xhi[e & 3][t] = xv.w;
        }
        float4 xnext = x_in[cb + (size_t)clampr(e+1)*W4];
        __syncthreads();

        // ---- S1: row j1 = e-1, active j1 in [h0-2, h0+TH+1]
        float4 ov = z, bnew = z;
        if (e >= h0-1 && e <= h0+TH+2) {
            const int j1 = e - 1;
            float lw = xhi[j1 & 3][tm];
            float rx = xlo[j1 & 3][tp];
            float4 bv;
            if (SAME_XB) bv = xm1;                      // b == x0
            else bv = b_in[cb + (size_t)clampr(j1)*W4];
            bnew = bv;
            ov = stage(j1, xm1, xm2, xv, lw, rx, bv, ta);
            ylo[j1 & 3][t] = ov.x;
            yhi[j1 & 3][t] = ov.w;
        }

        // ---- S2: row j2 = e-3, active j2 in [h0-1, h0+TH]
        float4 pv = z;
        if (e >= h0+2 && e <= h0+TH+3) {
            const int j2 = e - 3;
            float lw = yhi[j2 & 3][tm];
            float rx = ylo[j2 & 3][tp];
            pv = stage(j2, y1, y2, y0, lw, rx, bf1, tb);
            plo[j2 & 3][t] = pv.x;
            phi[j2 & 3][t] = pv.w;
        }

        // ---- S3: row j3 = e-5, outputs h0 .. h0+TH-1 (always real rows)
        if (e >= h0+5) {
            const int j3 = e - 5;
            float lw = phi[j3 & 3][tm];
            float rx = plo[j3 & 3][tp];
            float4 bv = b_in[cb + (size_t)j3*W4];       // L1-resident reload
            float4 on = stage(j3, z1, z2, z0, lw, rx, bv, tc);
            x_out[cb + (size_t)j3*W4] = on;
        }

        // ---- FIFO shifts (renamed away by the x4 unroll)
        z2 = z1; z1 = z0; z0 = pv;
        y2 = y1; y1 = y0; y0 = ov;
        bf1 = bf0; bf0 = bnew;
        xm2 = xm1; xm1 = xv; xv = xnext;
    }
}

// -------------------- launch --------------------
extern "C" void kernel_launch(void* const* d_in, const int* in_sizes, int n_in,
                              void* d_out, int out_size)
{
    const float4* ae  = (const float4*)d_in[0];   // (B,D,H,W) fp32
    const float*  wxy = (const float*)d_in[1];    // (B,2,H,W)
    float4* out = (float4*)d_out;                 // (B,D,H,W)

    float4* xb;
    cudaGetSymbolAddress((void**)&xb, g_x);
    float4* xA = xb;
    float4* xB = xb + NV4;

    // 12 Chebyshev roots on [1,9]: a_k = 5 - 4 cos((2k+1)pi/24).
    // Same extreme-paired sequence as R8..R13 (identical arithmetic).
    double a[12];
    for (int k = 0; k < 12; ++k)
        a[k] = 5.0 - 4.0 * cos((2.0*k + 1.0) * M_PI / 24.0);
    const int ord[12] = {0,11, 1,10, 2,9, 3,8, 4,7, 5,6};
    float tau[12];
    for (int s = 0; s < 12; ++s) tau[s] = (float)(1.0 / a[ord[s]]);

    const int GRID = BB * NCHUNK * 2;   // 256 blocks x 320 threads -> 2/SM

    rich_tri<1><<<GRID, NT>>>(ae, ae, wxy, xA, tau[0], tau[1], tau[2]);
    rich_tri<0><<<GRID, NT>>>(xA, ae, wxy, xB, tau[3], tau[4], tau[5]);
    rich_tri<0><<<GRID, NT>>>(xB, ae, wxy, xA, tau[6], tau[7], tau[8]);
    rich_tri<0><<<GRID, NT>>>(xA, ae, wxy, out, tau[9], tau[10], tau[11]);
}

// round 15
// speedup vs baseline: 2.0331x; 1.0878x over previous
#include <cuda_runtime.h>
#include <math.h>

// Problem constants
#define BB 16
#define DD 16
#define HH 128
#define WW 160
#define W4 (WW/4)            // 40 float4 per (image,channel,row)
#define NCH 4                // channels per block
#define NT (NCH*W4)          // 160 threads = 5 warps
#define TH 16                // output rows per block
#define NCHUNK (HH/TH)       // 8
#define HW (HH*WW)
#define PL4 (HH*W4)          // float4 per channel plane
#define NV4 (BB*DD*PL4)

__device__ float4 g_x[2][NV4];    // x ping-pong, native (B,D,H,W) layout

__device__ __forceinline__ int clampr(int r) {
    return r < 0 ? 0 : (r > HH-1 ? HH-1 : r);
}

// -------------------- fused TRIPLE Richardson step, w-vectorized ----------
// S1: x1 = x  + ta*(b - A x)   at row e-1
// S2: x2 = x1 + tb*(b - A x1)  at row e-3
// S3: x3 = x2 + tc*(b - A x2)  at row e-5  (stored)
// Thread t = ch*40 + wb holds [bi][cg*4+ch][row][4*wb..4*wb+3].
// Horizontal: in-register; 2 boundary scalars per stage via smem edge rings
// (depth 4). Vertical: per-thread register FIFOs (R11/R13 timeline):
//   epoch e: xm1=x(e-1) xm2=x(e-2) xv=x(e); y*=x1(e-2..e-4); z*=x2(e-4..e-6);
//   bf1=b(e-3); S3 reloads b(e-5) (L1/L2-resident).
// Ring audit identical to R13/R14 (write/read slots differ by 2 mod 4).
// Channel-boundary garbage at t+-1 is multiplied by exact-zero wx edge
// weights (reference padding); block-edge clamps likewise masked.
// 160-thread blocks, 4 per SM: independent barrier domains hide each
// other's sync/scoreboard stalls.
template<int SAME_XB>
__global__ void __launch_bounds__(NT, 4)
rich_tri(const float4* __restrict__ x_in,
         const float4* __restrict__ b_in,
         const float*  __restrict__ wxy,
         float4* __restrict__ x_out,
         float ta, float tb, float tc)
{
    __shared__ float xlo[4][NT], xhi[4][NT];
    __shared__ float ylo[4][NT], yhi[4][NT];
    __shared__ float plo[4][NT], phi[4][NT];

    const int t  = threadIdx.x;        // 160
    const int ch = t / W4;             // 0..3
    const int wb = t - ch*W4;
    const int blk = blockIdx.x;
    const int cg  = blk & 3;           // channel group (4 groups of 4)
    const int r2  = blk >> 2;
    const int bi  = r2 >> 3;           // r2 / NCHUNK
    const int h0  = (r2 & 7) << 4;     // chunk*TH, low 4 bits zero

    const size_t cb = ((size_t)(bi*DD + cg*NCH + ch))*PL4 + wb;
    const float* wxb = wxy + (size_t)bi*2*HW + wb*4;
    const float* wyb = wxb + HW;
    const int tm = t > 0 ? t-1 : 0;
    const int tp = t < NT-1 ? t+1 : NT-1;
    const float4 z = {0.f,0.f,0.f,0.f};

    // one Richardson stage at row j: o = c + tau*(b - (c + lap))
    auto stage = [&](int j, float4 c, float4 u, float4 d,
                     float lw, float rx, float4 bv, float tau) -> float4 {
        const int jc = clampr(j);
        const float* wxr = wxb + jc*WW;
        float4 wxv = *(const float4*)wxr;
        float  wxl = (wb > 0) ? wxr[-1] : 0.f;
        if (wb == W4-1) wxv.w = 0.f;
        float4 wyd = *(const float4*)(wyb + jc*WW);
        float4 wyu = *(const float4*)(wyb + clampr(j-1)*WW);
        if (j <= 0)     wyu = z;
        if (j >= HH-1)  wyd = z;

        float hxm = wxl   * (c.x - lw);
        float hx0 = wxv.x * (c.y - c.x);
        float hx1 = wxv.y * (c.z - c.y);
        float hx2 = wxv.z * (c.w - c.z);
        float hx3 = wxv.w * (rx  - c.w);

        float4 lap;
        lap.x = (hxm - hx0) + wyu.x*(c.x - u.x) - wyd.x*(d.x - c.x);
        lap.y = (hx0 - hx1) + wyu.y*(c.y - u.y) - wyd.y*(d.y - c.y);
        lap.z = (hx1 - hx2) + wyu.z*(c.z - u.z) - wyd.z*(d.z - c.z);
        lap.w = (hx2 - hx3) + wyu.w*(c.w - u.w) - wyd.w*(d.w - c.w);

        float4 o;
        o.x = c.x + tau*(bv.x - c.x - lap.x);
        o.y = c.y + tau*(bv.y - c.y - lap.y);
        o.z = c.z + tau*(bv.z - c.z - lap.z);
        o.w = c.w + tau*(bv.w - c.w - lap.w);
        return o;
    };

    // register FIFOs
    float4 xm2 = z, xm1 = z;
    float4 y0 = z, y1 = z, y2 = z;
    float4 z0 = z, z1 = z, z2 = z;
    float4 bf0 = z, bf1 = z;

    float4 xv = x_in[cb + (size_t)clampr(h0-3)*W4];

    #pragma unroll 4
    for (int i = 0; i < TH+8; ++i) {           // e = h0-3 .. h0+TH+4
        const int e = h0 - 3 + i;

        // ---- S0: publish edge scalars of x row e; prefetch row e+1
        if (e <= h0+TH+2) {
            xlo[e & 3][t] = xv.x;
            xhi[e & 3][t] = xv.w;
        }
        float4 xnext = x_in[cb + (size_t)clampr(e+1)*W4];
        __syncthreads();

        // ---- S1: row j1 = e-1, active j1 in [h0-2, h0+TH+1]
        float4 ov = z, bnew = z;
        if (e >= h0-1 && e <= h0+TH+2) {
            const int j1 = e - 1;
            float lw = xhi[j1 & 3][tm];
            float rx = xlo[j1 & 3][tp];
            float4 bv;
            if (SAME_XB) bv = xm1;                      // b == x0
            else bv = b_in[cb + (size_t)clampr(j1)*W4];
            bnew = bv;
            ov = stage(j1, xm1, xm2, xv, lw, rx, bv, ta);
            ylo[j1 & 3][t] = ov.x;
            yhi[j1 & 3][t] = ov.w;
        }

        // ---- S2: row j2 = e-3, active j2 in [h0-1, h0+TH]
        float4 pv = z;
        if (e >= h0+2 && e <= h0+TH+3) {
            const int j2 = e - 3;
            float lw = yhi[j2 & 3][tm];
            float rx = ylo[j2 & 3][tp];
            pv = stage(j2, y1, y2, y0, lw, rx, bf1, tb);
            plo[j2 & 3][t] = pv.x;
            phi[j2 & 3][t] = pv.w;
        }

        // ---- S3: row j3 = e-5, outputs h0 .. h0+TH-1 (always real rows)
        if (e >= h0+5) {
            const int j3 = e - 5;
            float lw = phi[j3 & 3][tm];
            float rx = plo[j3 & 3][tp];
            float4 bv = b_in[cb + (size_t)j3*W4];       // cache-resident reload
            float4 on = stage(j3, z1, z2, z0, lw, rx, bv, tc);
            x_out[cb + (size_t)j3*W4] = on;
        }

        // ---- FIFO shifts (renamed away by the x4 unroll)
        z2 = z1; z1 = z0; z0 = pv;
        y2 = y1; y1 = y0; y0 = ov;
        bf1 = bf0; bf0 = bnew;
        xm2 = xm1; xm1 = xv; xv = xnext;
    }
}

// -------------------- launch --------------------
extern "C" void kernel_launch(void* const* d_in, const int* in_sizes, int n_in,
                              void* d_out, int out_size)
{
    const float4* ae  = (const float4*)d_in[0];   // (B,D,H,W) fp32
    const float*  wxy = (const float*)d_in[1];    // (B,2,H,W)
    float4* out = (float4*)d_out;                 // (B,D,H,W)

    float4* xb;
    cudaGetSymbolAddress((void**)&xb, g_x);
    float4* xA = xb;
    float4* xB = xb + NV4;

    // 12 Chebyshev roots on [1,9]: a_k = 5 - 4 cos((2k+1)pi/24).
    // Same extreme-paired sequence as R8..R14 (identical arithmetic).
    double a[12];
    for (int k = 0; k < 12; ++k)
        a[k] = 5.0 - 4.0 * cos((2.0*k + 1.0) * M_PI / 24.0);
    const int ord[12] = {0,11, 1,10, 2,9, 3,8, 4,7, 5,6};
    float tau[12];
    for (int s = 0; s < 12; ++s) tau[s] = (float)(1.0 / a[ord[s]]);

    const int GRID = BB * NCHUNK * 4;   // 512 blocks x 160 threads -> ~4/SM

    rich_tri<1><<<GRID, NT>>>(ae, ae, wxy, xA, tau[0], tau[1], tau[2]);
    rich_tri<0><<<GRID, NT>>>(xA, ae, wxy, xB, tau[3], tau[4], tau[5]);
    rich_tri<0><<<GRID, NT>>>(xB, ae, wxy, xA, tau[6], tau[7], tau[8]);
    rich_tri<0><<<GRID, NT>>>(xA, ae, wxy, out, tau[9], tau[10], tau[11]);
}